// round 13
// baseline (speedup 1.0000x reference)
#include <cuda_runtime.h>
#include <cuda_bf16.h>
#include <cstdint>

#define DEVINL __device__ __forceinline__

constexpr int BB = 256;            // batch
constexpr int II = 512;            // input dim
constexpr int RR = 1024;           // hidden dim
constexpr int UU = 11;             // unroll length
constexpr int NSTEP = 10;          // steps that matter (step 10 is dead)
constexpr int OUTLD = UU * RR;     // output row stride
constexpr int PRELD = NSTEP * 4 * RR;

constexpr int BM  = 128;           // CTA m-tile
constexpr int KC  = 128;           // k-chunk elems (256 B per row)
constexpr int RW  = 68;            // smem row stride in words (256B data + 16B pad)
constexpr int NST = 2;             // pipeline stages
constexpr int A_ROWS = 128, B_ROWS = 64;
constexpr int A_STAGE = A_ROWS * RW;            // words
constexpr int B_STAGE = B_ROWS * RW;            // words
constexpr int SMEM_WORDS = NST * (A_STAGE + B_STAGE);
constexpr int SMEM_DYN   = SMEM_WORDS * 4;      // 104,448 B
constexpr int STAGE_BYTES = (A_ROWS + B_ROWS) * KC * 2;  // 49,152
constexpr int WBLK = 4 * RR * RR;  // one weight block (elems)
constexpr int NCVT_CTAS = 40;      // shadow-convert CTAs in k_step
constexpr int CVU = 16;            // convert unroll (MLP per thread)

// ---- scratch (__device__ globals; no allocation allowed) ----
__device__ __align__(16) __nv_bfloat16 g_Wi0b[(size_t)NSTEP * 4 * RR * II];
__device__ __align__(16) __nv_bfloat16 g_Wh0b[(size_t)NSTEP * WBLK];
__device__ __align__(16) __nv_bfloat16 g_Wi1b[(size_t)NSTEP * WBLK];
__device__ __align__(16) __nv_bfloat16 g_Wh1b[(size_t)NSTEP * WBLK];
__device__ __align__(16) __nv_bfloat16 g_xb[BB * II];
__device__ __align__(16) __nv_bfloat16 g_h0b[2][BB * RR];
__device__ __align__(16) __nv_bfloat16 g_h1b[2][BB * RR];
__device__ __align__(16) float g_preX[(size_t)BB * PRELD];
__device__ __align__(16) float g_c0[BB * RR];
__device__ __align__(16) float g_c1[BB * RR];

// ---- mbarrier / bulk-copy primitives ----
DEVINL void mbar_init(uint32_t a, uint32_t cnt) {
    asm volatile("mbarrier.init.shared.b64 [%0], %1;" :: "r"(a), "r"(cnt) : "memory");
}
DEVINL void mbar_expect(uint32_t a, uint32_t tx) {
    asm volatile("mbarrier.arrive.expect_tx.shared.b64 _, [%0], %1;"
                 :: "r"(a), "r"(tx) : "memory");
}
DEVINL void mbar_wait(uint32_t a, uint32_t parity) {
    asm volatile(
        "{\n\t.reg .pred P;\n"
        "WL_%=:\n\t"
        "mbarrier.try_wait.parity.acquire.cta.shared::cta.b64 P, [%0], %1, 0x989680;\n\t"
        "@P bra WD_%=;\n\t"
        "bra WL_%=;\n"
        "WD_%=:\n\t}"
        :: "r"(a), "r"(parity) : "memory");
}
DEVINL void bulk_cp(uint32_t dst, const void* src, uint32_t bytes, uint32_t mbar) {
    asm volatile(
        "cp.async.bulk.shared::cta.global.mbarrier::complete_tx::bytes [%0], [%1], %2, [%3];"
        :: "r"(dst), "l"(src), "r"(bytes), "r"(mbar) : "memory");
}

DEVINL void ldsm4(uint32_t& r0, uint32_t& r1, uint32_t& r2, uint32_t& r3, uint32_t a) {
    asm volatile("ldmatrix.sync.aligned.m8n8.x4.shared.b16 {%0,%1,%2,%3}, [%4];"
                 : "=r"(r0), "=r"(r1), "=r"(r2), "=r"(r3) : "r"(a));
}

DEVINL void mma16(float* d, const uint32_t* a, const uint32_t* b) {
    asm volatile(
        "mma.sync.aligned.m16n8k16.row.col.f32.bf16.bf16.f32 "
        "{%0,%1,%2,%3}, {%4,%5,%6,%7}, {%8,%9}, {%0,%1,%2,%3};"
        : "+f"(d[0]), "+f"(d[1]), "+f"(d[2]), "+f"(d[3])
        : "r"(a[0]), "r"(a[1]), "r"(a[2]), "r"(a[3]), "r"(b[0]), "r"(b[1]));
}

DEVINL float sigm(float x) { return 1.0f / (1.0f + expf(-x)); }

DEVINL uint2 pack_bf16x4(float4 v) {
    __nv_bfloat162 lo = __floats2bfloat162_rn(v.x, v.y);
    __nv_bfloat162 hi = __floats2bfloat162_rn(v.z, v.w);
    uint2 o;
    o.x = *reinterpret_cast<uint32_t*>(&lo);
    o.y = *reinterpret_cast<uint32_t*>(&hi);
    return o;
}

// bf16 TN GEMM body, bulk-TMA fed. CTA tile 128m x 64n (4 gates x 16 r),
// 256 thr = 8 warps (4m x 2n of 32m x 32n). W rows for gate g at
// nbase + g*gstride + r. Fill: KC=128 (256B/row), one cp.async.bulk per row
// per stage (192 rows), mbarrier expect_tx/parity double-buffer.
//   EPI 0: precompute -> acc + e0[col] + e1[col] into houtf (PreX, fp32)
//   EPI 1: layer0 cell -> base = PreX, state c0, write h0_next (bf16)
//   EPI 2: layer1 cell -> base = bi1+bh1, state c1, write h1 (fp32 out + bf16)
template<int EPI, int NPAIRS>
DEVINL void gemm_body(uint32_t* sm, int m0, int nbase,
                      const __nv_bfloat16* __restrict__ A0, int lda0,
                      const __nv_bfloat16* __restrict__ W0,
                      const __nv_bfloat16* __restrict__ A1, int lda1,
                      const __nv_bfloat16* __restrict__ W1,
                      int K, int gstride,
                      const float* __restrict__ e0,
                      const float* __restrict__ e1,
                      float* __restrict__ cst,
                      float* __restrict__ houtf, int ldh,
                      __nv_bfloat16* __restrict__ houtb)
{
    __shared__ __align__(8) uint64_t mbars[2];

    const int tid  = threadIdx.x;
    const int warp = tid >> 5, lane = tid & 31;
    const int wm = warp >> 1, wn = warp & 1;       // 4m x 2n warps
    const int gid = lane >> 2, tig = lane & 3;

    const uint32_t smu = (uint32_t)__cvta_generic_to_shared(sm);
    const uint32_t mb[2] = {
        (uint32_t)__cvta_generic_to_shared(&mbars[0]),
        (uint32_t)__cvta_generic_to_shared(&mbars[1]) };

    if (tid == 0) { mbar_init(mb[0], 1); mbar_init(mb[1], 1); }
    __syncthreads();

    // ---- loader: one row per thread (A: tid<128; B: 128<=tid<192) ----
    const char* src[2] = { nullptr, nullptr };
    uint32_t drow = 0, dstage = 0;
    if (tid < A_ROWS) {
        drow = (uint32_t)(tid * RW); dstage = A_STAGE;
        #pragma unroll
        for (int p = 0; p < NPAIRS; p++) {
            const __nv_bfloat16* A = (p == 0) ? A0 : A1;
            const int lda = (p == 0) ? lda0 : lda1;
            src[p] = (const char*)(A + (size_t)(m0 + tid) * lda);
        }
    } else if (tid < A_ROWS + B_ROWS) {
        const int rB = tid - A_ROWS;
        drow = (uint32_t)(NST * A_STAGE + rB * RW); dstage = B_STAGE;
        const int grow = nbase + (rB >> 4) * gstride + (rB & 15);
        #pragma unroll
        for (int p = 0; p < NPAIRS; p++) {
            const __nv_bfloat16* W = (p == 0) ? W0 : W1;
            src[p] = (const char*)(W + (size_t)grow * K);
        }
    }
    const bool loader = (tid < A_ROWS + B_ROWS);

    const int nk = K / KC;
    const int T  = NPAIRS * nk;

    auto issue = [&](int ci, int buf) {
        if (loader) {
            const int p    = (NPAIRS == 2 && ci >= nk) ? 1 : 0;
            const int koff = ((p ? ci - nk : ci) * KC) * 2;   // bytes
            bulk_cp(smu + (drow + (uint32_t)buf * dstage) * 4,
                    src[p] + koff, KC * 2, mb[buf]);
        }
    };

    // ldmatrix lane-derived coordinates
    const int a_row = 32 * wm + (lane & 15);
    const int a_wof = (lane >> 4) << 2;
    const int b_row = ((lane >> 4) & 1) * 16 + 8 * wn + (lane & 7);
    const int b_wof = ((lane >> 3) & 1) << 2;

    float acc[2][4][4];
    #pragma unroll
    for (int a = 0; a < 2; a++)
        #pragma unroll
        for (int g = 0; g < 4; g++)
            #pragma unroll
            for (int c = 0; c < 4; c++) acc[a][g][c] = 0.0f;

    // ---- prologue: fill both stages ----
    if (tid == 0) mbar_expect(mb[0], STAGE_BYTES);
    __syncthreads();
    issue(0, 0);
    if (tid == 0) mbar_expect(mb[1], STAGE_BYTES);
    __syncthreads();
    issue(1, 1);

    int ph[2] = { 0, 0 };

    #pragma unroll 1
    for (int t = 0; t < T; t++) {
        const int buf = t & 1;
        mbar_wait(mb[buf], (uint32_t)ph[buf]);
        ph[buf] ^= 1;

        const uint32_t Abase = smu + ((uint32_t)buf * A_STAGE) * 4;
        const uint32_t Bbase = smu + ((uint32_t)(NST * A_STAGE) + (uint32_t)buf * B_STAGE) * 4;

        #pragma unroll
        for (int ks = 0; ks < KC / 16; ks++) {        // 8 k16 slices
            const int kw0 = ks * 8;
            uint32_t ua[2][4];
            #pragma unroll
            for (int mi = 0; mi < 2; mi++)
                ldsm4(ua[mi][0], ua[mi][1], ua[mi][2], ua[mi][3],
                      Abase + (uint32_t)((a_row + 16 * mi) * RW + kw0 + a_wof) * 4);
            uint32_t ub[4][2];
            #pragma unroll
            for (int gp = 0; gp < 2; gp++)
                ldsm4(ub[2 * gp][0], ub[2 * gp][1],
                      ub[2 * gp + 1][0], ub[2 * gp + 1][1],
                      Bbase + (uint32_t)((b_row + 32 * gp) * RW + kw0 + b_wof) * 4);
            #pragma unroll
            for (int mi = 0; mi < 2; mi++)
                #pragma unroll
                for (int g = 0; g < 4; g++)
                    mma16(acc[mi][g], ua[mi], ub[g]);
        }

        if (t + 2 < T) {
            __syncthreads();                          // all reads of buf done
            if (tid == 0) mbar_expect(mb[buf], STAGE_BYTES);
            __syncthreads();                          // expect visible
            issue(t + 2, buf);
        }
    }

    // ---- epilogue ----
    #pragma unroll
    for (int mi = 0; mi < 2; mi++) {
        #pragma unroll
        for (int half = 0; half < 2; half++) {
            const int row = 32 * wm + 16 * mi + gid + 8 * half;
            const int b = m0 + row;
            #pragma unroll
            for (int cc = 0; cc < 2; cc++) {
                const int reg = 2 * half + cc;
                const int rl = 8 * wn + 2 * tig + cc;
                if constexpr (EPI == 0) {
                    #pragma unroll
                    for (int g = 0; g < 4; g++) {
                        const int col = nbase + g * gstride + rl;
                        houtf[(size_t)b * ldh + col] = acc[mi][g][reg] + e0[col] + e1[col];
                    }
                } else {
                    const int r = nbase + rl;
                    float pre[4];
                    #pragma unroll
                    for (int g = 0; g < 4; g++) {
                        float base;
                        if constexpr (EPI == 1)
                            base = e0[(size_t)b * PRELD + g * RR + r];
                        else
                            base = e0[g * RR + r] + e1[g * RR + r];
                        pre[g] = acc[mi][g][reg] + base;
                    }
                    const float cprev = cst[b * RR + r];
                    const float iv = sigm(pre[0]);
                    const float fv = sigm(pre[1]);
                    const float ov = sigm(pre[2]);
                    const float gv = tanhf(pre[3]);
                    const float cnew = fv * cprev + iv * gv;
                    const float hnew = ov * tanhf(cnew);
                    cst[b * RR + r] = cnew;
                    houtb[b * RR + r] = __float2bfloat16_rn(hnew);
                    if constexpr (EPI == 2)
                        houtf[(size_t)b * ldh + r] = hnew;
                }
            }
        }
    }
}

// ---- kernels ----

__global__ __launch_bounds__(256, 2)
void k_pre(const float* __restrict__ bi0, const float* __restrict__ bh0,
           float* __restrict__ preX)
{
    extern __shared__ uint32_t smraw[];
    const int rg = blockIdx.y * 16;
    const int u = rg >> 10, rb = rg & 1023;
    const int nbase = u * 4096 + rb;
    gemm_body<0, 1>(smraw, blockIdx.x * BM, nbase,
                    g_xb, II, g_Wi0b, nullptr, 0, nullptr,
                    II, RR, bi0, bh0, nullptr, preX, PRELD, nullptr);
}

__global__ __launch_bounds__(256, 2)
void k_l0(const __nv_bfloat16* __restrict__ h0cur, const __nv_bfloat16* __restrict__ Wh0u,
          const float* __restrict__ preXu, float* __restrict__ c0,
          __nv_bfloat16* __restrict__ h0nxt)
{
    extern __shared__ uint32_t smraw[];
    gemm_body<1, 1>(smraw, blockIdx.x * BM, blockIdx.y * 16,
                    h0cur, RR, Wh0u, nullptr, 0, nullptr,
                    RR, RR, preXu, nullptr, c0, nullptr, 0, h0nxt);
}

__global__ __launch_bounds__(256, 2)
void k_l1(const __nv_bfloat16* __restrict__ h0cur, const __nv_bfloat16* __restrict__ Wi1u,
          const __nv_bfloat16* __restrict__ h1in, const __nv_bfloat16* __restrict__ Wh1u,
          const float* __restrict__ bi1u, const float* __restrict__ bh1u,
          float* __restrict__ c1, float* __restrict__ h1outf,
          __nv_bfloat16* __restrict__ h1outb)
{
    extern __shared__ uint32_t smraw[];
    gemm_body<2, 2>(smraw, blockIdx.x * BM, blockIdx.y * 16,
                    h0cur, RR, Wi1u, h1in, RR, Wh1u,
                    RR, RR, bi1u, bh1u, c1, h1outf, OUTLD, h1outb);
}

// Combined step + shadow convert:
//   y < 64   : L1(u)  (K=2048)
//   y 64..127: L0(u+1) (K=1024)
//   y >= 128 : convert NEXT step's Wi1/Wh1 fp32->bf16 (batched MLP=CVU)
// Grid (2, 128 + NCVT_CTAS/2) = 296 CTAs = one full wave at 2 CTAs/SM.
__global__ __launch_bounds__(256, 2)
void k_step(const __nv_bfloat16* __restrict__ h0cur, __nv_bfloat16* __restrict__ h0nxt,
            const __nv_bfloat16* __restrict__ Wi1u, const __nv_bfloat16* __restrict__ Wh1u,
            const float* __restrict__ bi1u, const float* __restrict__ bh1u,
            const __nv_bfloat16* __restrict__ h1in, float* __restrict__ h1outf,
            __nv_bfloat16* __restrict__ h1outb,
            const __nv_bfloat16* __restrict__ Wh0n, const float* __restrict__ preXn,
            float* __restrict__ c0, float* __restrict__ c1,
            const float4* __restrict__ cs0, uint2* __restrict__ cd0,
            const float4* __restrict__ cs1, uint2* __restrict__ cd1)
{
    const int y = blockIdx.y;
    if (y >= 128) {
        const int cid  = blockIdx.x * (NCVT_CTAS / 2) + (y - 128);
        const int nthr = NCVT_CTAS * 256;
        const int t0   = cid * 256 + threadIdx.x;
        const int n4   = WBLK / 4;
        #pragma unroll 1
        for (int b = 0; b < 2; b++) {
            const float4* s = (b == 0) ? cs0 : cs1;
            uint2*        d = (b == 0) ? cd0 : cd1;
            #pragma unroll 1
            for (int i = t0; i < n4; i += nthr * CVU) {
                float4 v[CVU];
                #pragma unroll
                for (int j = 0; j < CVU; j++) {
                    const int idx = i + j * nthr;
                    if (idx < n4) v[j] = s[idx];
                }
                #pragma unroll
                for (int j = 0; j < CVU; j++) {
                    const int idx = i + j * nthr;
                    if (idx < n4) d[idx] = pack_bf16x4(v[j]);
                }
            }
        }
        return;
    }
    extern __shared__ uint32_t smraw[];
    const int m0 = blockIdx.x * BM;
    if (y < 64) {
        gemm_body<2, 2>(smraw, m0, y * 16,
                        h0cur, RR, Wi1u, h1in, RR, Wh1u,
                        RR, RR, bi1u, bh1u, c1, h1outf, OUTLD, h1outb);
    } else {
        gemm_body<1, 1>(smraw, m0, (y - 64) * 16,
                        h0cur, RR, Wh0n, nullptr, 0, nullptr,
                        RR, RR, preXn, nullptr, c0, nullptr, 0, h0nxt);
    }
}

// fp32 -> bf16 streaming convert
__global__ void k_cvt(const float4* __restrict__ in, uint2* __restrict__ out, int n4) {
    int i = blockIdx.x * blockDim.x + threadIdx.x;
    if (i >= n4) return;
    out[i] = pack_bf16x4(in[i]);
}

__global__ void init_states(const float* __restrict__ st, float* __restrict__ out) {
    int idx = blockIdx.x * blockDim.x + threadIdx.x;
    if (idx >= BB * RR) return;
    int b = idx >> 10, r = idx & (RR - 1);
    const float* s = st + (size_t)b * (4 * RR);
    g_h0b[0][idx] = __float2bfloat16_rn(s[r]);
    g_c0[idx]     = s[RR + r];
    float h1 = s[2 * RR + r];
    g_h1b[0][idx] = __float2bfloat16_rn(h1);
    out[(size_t)b * OUTLD + r] = h1;
    g_c1[idx]     = s[3 * RR + r];
}

extern "C" void kernel_launch(void* const* d_in, const int* in_sizes, int n_in,
                              void* d_out, int out_size)
{
    const float* x   = (const float*)d_in[0];
    const float* ini = (const float*)d_in[1];
    const float* Wi0 = (const float*)d_in[2];
    const float* bi0 = (const float*)d_in[3];
    const float* Wh0 = (const float*)d_in[4];
    const float* bh0 = (const float*)d_in[5];
    const float* Wi1 = (const float*)d_in[6];
    const float* bi1 = (const float*)d_in[7];
    const float* Wh1 = (const float*)d_in[8];
    const float* bh1 = (const float*)d_in[9];
    float* out = (float*)d_out;

    static bool attr_done = false;
    if (!attr_done) {
        cudaFuncSetAttribute(k_pre,  cudaFuncAttributeMaxDynamicSharedMemorySize, SMEM_DYN);
        cudaFuncSetAttribute(k_l0,   cudaFuncAttributeMaxDynamicSharedMemorySize, SMEM_DYN);
        cudaFuncSetAttribute(k_l1,   cudaFuncAttributeMaxDynamicSharedMemorySize, SMEM_DYN);
        cudaFuncSetAttribute(k_step, cudaFuncAttributeMaxDynamicSharedMemorySize, SMEM_DYN);
        attr_done = true;
    }

    float *preX, *c0, *c1;
    __nv_bfloat16 *wi0b, *wh0b, *wi1b, *wh1b, *xb, *h0b, *h1b;
    cudaGetSymbolAddress((void**)&preX, g_preX);
    cudaGetSymbolAddress((void**)&c0,   g_c0);
    cudaGetSymbolAddress((void**)&c1,   g_c1);
    cudaGetSymbolAddress((void**)&wi0b, g_Wi0b);
    cudaGetSymbolAddress((void**)&wh0b, g_Wh0b);
    cudaGetSymbolAddress((void**)&wi1b, g_Wi1b);
    cudaGetSymbolAddress((void**)&wh1b, g_Wh1b);
    cudaGetSymbolAddress((void**)&xb,   g_xb);
    cudaGetSymbolAddress((void**)&h0b,  g_h0b);
    cudaGetSymbolAddress((void**)&h1b,  g_h1b);

    auto h0p = [&](int i) { return h0b + (size_t)i * BB * RR; };
    auto h1p = [&](int i) { return h1b + (size_t)i * BB * RR; };

    auto cvt = [&](const float* src, __nv_bfloat16* dst, size_t n) {
        int n4 = (int)(n / 4);
        k_cvt<<<(n4 + 255) / 256, 256>>>((const float4*)src, (uint2*)dst, n4);
    };

    // ---- upfront converts: x, Wi0 (k_pre), ALL Wh0, Wi1[0], Wh1[0] ----
    cvt(x,   xb,   (size_t)BB * II);
    cvt(Wi0, wi0b, (size_t)NSTEP * 4 * RR * II);
    cvt(Wh0, wh0b, (size_t)NSTEP * WBLK);
    cvt(Wi1, wi1b, (size_t)WBLK);
    cvt(Wh1, wh1b, (size_t)WBLK);

    init_states<<<(BB * RR) / 256, 256>>>(ini, out);

    // PreX = x @ Wi0[0:10].T + bi0 + bh0
    k_pre<<<dim3(BB / BM, PRELD / 64), 256, SMEM_DYN>>>(bi0, bh0, preX);

    // L0(0)
    k_l0<<<dim3(BB / BM, RR / 16), 256, SMEM_DYN>>>(h0p(0), wh0b, preX, c0, h0p(1));

    // C(u) = L1(u) + L0(u+1) + shadow-convert(Wi1[u+1], Wh1[u+1]), u = 0..8
    for (int u = 0; u < NSTEP - 1; u++) {
        const size_t wo  = (size_t)u * WBLK;
        const size_t wn_ = (size_t)(u + 1) * WBLK;
        const size_t bo  = (size_t)u * 4 * RR;
        k_step<<<dim3(BB / BM, 128 + NCVT_CTAS / 2), 256, SMEM_DYN>>>(
            h0p((u + 1) & 1), h0p(u & 1),
            wi1b + wo, wh1b + wo, bi1 + bo, bh1 + bo,
            h1p(u & 1), out + (size_t)(u + 1) * RR, h1p((u + 1) & 1),
            wh0b + wn_, preX + (size_t)(u + 1) * 4 * RR,
            c0, c1,
            (const float4*)(Wi1 + wn_), (uint2*)(wi1b + wn_),
            (const float4*)(Wh1 + wn_), (uint2*)(wh1b + wn_));
    }

    // final L1(9)
    {
        const int u = NSTEP - 1;
        const size_t wo = (size_t)u * WBLK;
        const size_t bo = (size_t)u * 4 * RR;
        k_l1<<<dim3(BB / BM, RR / 16), 256, SMEM_DYN>>>(
            h0p((u + 1) & 1), wi1b + wo,
            h1p(u & 1), wh1b + wo,
            bi1 + bo, bh1 + bo,
            c1, out + (size_t)(u + 1) * RR, h1p((u + 1) & 1));
    }
}

// round 14
// speedup vs baseline: 1.0468x; 1.0468x over previous
#include <cuda_runtime.h>
#include <cuda_bf16.h>
#include <cstdint>

#define DEVINL __device__ __forceinline__

constexpr int BB = 256;            // batch
constexpr int II = 512;            // input dim
constexpr int RR = 1024;           // hidden dim
constexpr int UU = 11;             // unroll length
constexpr int NSTEP = 10;          // steps that matter (step 10 is dead)
constexpr int OUTLD = UU * RR;     // output row stride
constexpr int PRELD = NSTEP * 4 * RR;

constexpr int BM  = 128;           // CTA m-tile
constexpr int KC  = 32;            // k-chunk (bf16 elems = 64 bytes)
constexpr int AW  = 20;            // smem row stride in 32-bit words (16 data + 4 pad)
constexpr int NST = 3;             // pipeline stages
constexpr int WBLK = 4 * RR * RR;  // one weight block (elems)
constexpr int NCVT_CTAS = 40;      // shadow-convert CTAs in k_step
constexpr int CVU = 16;            // convert unroll (MLP per thread)

// merged-convert region boundaries (in float4 units)
constexpr int CV_N0 = BB * II / 4;                       // x
constexpr int CV_N1 = NSTEP * 4 * RR * II / 4;           // Wi0 (all)
constexpr int CV_N2 = NSTEP * WBLK / 4;                  // Wh0 (all)
constexpr int CV_N3 = WBLK / 4;                          // Wi1[0]
constexpr int CV_N4 = WBLK / 4;                          // Wh1[0]
constexpr int CV_C0 = CV_N0;
constexpr int CV_C1 = CV_C0 + CV_N1;
constexpr int CV_C2 = CV_C1 + CV_N2;
constexpr int CV_C3 = CV_C2 + CV_N3;
constexpr int CV_C4 = CV_C3 + CV_N4;                     // total

// ---- scratch (__device__ globals; no allocation allowed) ----
__device__ __align__(16) __nv_bfloat16 g_Wi0b[(size_t)NSTEP * 4 * RR * II];
__device__ __align__(16) __nv_bfloat16 g_Wh0b[(size_t)NSTEP * WBLK];
__device__ __align__(16) __nv_bfloat16 g_Wi1b[(size_t)NSTEP * WBLK];
__device__ __align__(16) __nv_bfloat16 g_Wh1b[(size_t)NSTEP * WBLK];
__device__ __align__(16) __nv_bfloat16 g_xb[BB * II];
__device__ __align__(16) __nv_bfloat16 g_h0b[2][BB * RR];
__device__ __align__(16) __nv_bfloat16 g_h1b[2][BB * RR];
__device__ __align__(16) float g_preX[(size_t)BB * PRELD];
__device__ __align__(16) float g_c0[BB * RR];
__device__ __align__(16) float g_c1[BB * RR];

DEVINL void cp16(void* s, const void* g) {
    uint32_t sa = (uint32_t)__cvta_generic_to_shared(s);
    asm volatile("cp.async.cg.shared.global [%0], [%1], 16;" :: "r"(sa), "l"(g));
}
DEVINL void cp_commit() { asm volatile("cp.async.commit_group;"); }
DEVINL void cp_wait0()  { asm volatile("cp.async.wait_group 0;"); }
DEVINL void cp_wait1()  { asm volatile("cp.async.wait_group 1;"); }

DEVINL void ldsm4(uint32_t& r0, uint32_t& r1, uint32_t& r2, uint32_t& r3,
                  const void* p) {
    uint32_t a = (uint32_t)__cvta_generic_to_shared(p);
    asm volatile("ldmatrix.sync.aligned.m8n8.x4.shared.b16 {%0,%1,%2,%3}, [%4];"
                 : "=r"(r0), "=r"(r1), "=r"(r2), "=r"(r3) : "r"(a));
}

DEVINL void mma16(float* d, const uint32_t* a, const uint32_t* b) {
    asm volatile(
        "mma.sync.aligned.m16n8k16.row.col.f32.bf16.bf16.f32 "
        "{%0,%1,%2,%3}, {%4,%5,%6,%7}, {%8,%9}, {%0,%1,%2,%3};"
        : "+f"(d[0]), "+f"(d[1]), "+f"(d[2]), "+f"(d[3])
        : "r"(a[0]), "r"(a[1]), "r"(a[2]), "r"(a[3]), "r"(b[0]), "r"(b[1]));
}

DEVINL float sigm(float x) { return 1.0f / (1.0f + expf(-x)); }

DEVINL uint2 pack_bf16x4(float4 v) {
    __nv_bfloat162 lo = __floats2bfloat162_rn(v.x, v.y);
    __nv_bfloat162 hi = __floats2bfloat162_rn(v.z, v.w);
    uint2 o;
    o.x = *reinterpret_cast<uint32_t*>(&lo);
    o.y = *reinterpret_cast<uint32_t*>(&hi);
    return o;
}

// bf16 TN GEMM body: CTA tile 128m x 64n (4 gates x 16 r), 256 thr = 8 warps
// (4m x 2n of 32m x 32n). W rows for gate g at nbase + g*gstride + r.
//   EPI 0: precompute -> acc + e0[col] + e1[col] into houtf (PreX, fp32)
//   EPI 1: layer0 cell -> base = PreX, state c0, write h0_next (bf16)
//   EPI 2: layer1 cell -> base = bi1+bh1, state c1, write h1 (fp32 out + bf16)
template<int EPI, int NPAIRS>
DEVINL void gemm_body(uint32_t (&As)[NST][BM][AW], uint32_t (&Bs)[NST][64][AW],
                      int m0, int nbase,
                      const __nv_bfloat16* __restrict__ A0, int lda0,
                      const __nv_bfloat16* __restrict__ W0,
                      const __nv_bfloat16* __restrict__ A1, int lda1,
                      const __nv_bfloat16* __restrict__ W1,
                      int K, int gstride,
                      const float* __restrict__ e0,
                      const float* __restrict__ e1,
                      float* __restrict__ cst,
                      float* __restrict__ houtf, int ldh,
                      __nv_bfloat16* __restrict__ houtb)
{
    const int tid  = threadIdx.x;
    const int warp = tid >> 5, lane = tid & 31;
    const int wm = warp >> 1, wn = warp & 1;       // 4m x 2n warps
    const int gid = lane >> 2, tig = lane & 3;

    const int lr = tid >> 2;                 // 0..63  (loader row)
    const int w  = tid & 3;                  // 16B segment -> bf16 offset 8w, word 4w

    // ldmatrix lane-derived coordinates
    const int a_row = 32 * wm + (lane & 15);
    const int a_wof = (lane >> 4) << 2;
    const int b_row = ((lane >> 4) & 1) * 16 + 8 * wn + (lane & 7);
    const int b_wof = ((lane >> 3) & 1) << 2;

    const __nv_bfloat16* Ag[NPAIRS];
    const __nv_bfloat16* Wg[NPAIRS];
    int ldaP[NPAIRS];
    #pragma unroll
    for (int p = 0; p < NPAIRS; p++) {
        const __nv_bfloat16* A = (p == 0) ? A0 : A1;
        const __nv_bfloat16* W = (p == 0) ? W0 : W1;
        ldaP[p] = (p == 0) ? lda0 : lda1;
        Ag[p] = A + (size_t)(m0 + lr) * ldaP[p] + 8 * w;
        const int grow = nbase + (lr >> 4) * gstride + (lr & 15);
        Wg[p] = W + (size_t)grow * K + 8 * w;
    }

    const int nk = K / KC;
    const int T  = NPAIRS * nk;

    float acc[2][4][4];
    #pragma unroll
    for (int a = 0; a < 2; a++)
        #pragma unroll
        for (int g = 0; g < 4; g++)
            #pragma unroll
            for (int c = 0; c < 4; c++) acc[a][g][c] = 0.0f;

    // --- prologue: chunks 0,1 ---
    #pragma unroll 1
    for (int ci = 0; ci < 2 && ci < T; ci++) {
        const int buf  = ci % NST;
        const int p    = (NPAIRS == 2 && ci >= nk) ? 1 : 0;
        const int koff = (p ? ci - nk : ci) * KC;
        #pragma unroll
        for (int i = 0; i < 2; i++)
            cp16(&As[buf][lr + 64 * i][4 * w],
                 Ag[p] + (size_t)(64 * i) * ldaP[p] + koff);
        cp16(&Bs[buf][lr][4 * w], Wg[p] + koff);
        cp_commit();
    }

    #pragma unroll 1
    for (int t = 0; t < T; t++) {
        if (t + 1 < T) cp_wait1(); else cp_wait0();
        __syncthreads();

        const int ci2 = t + 2;
        if (ci2 < T) {
            const int buf  = ci2 % NST;
            const int p    = (NPAIRS == 2 && ci2 >= nk) ? 1 : 0;
            const int koff = (p ? ci2 - nk : ci2) * KC;
            #pragma unroll
            for (int i = 0; i < 2; i++)
                cp16(&As[buf][lr + 64 * i][4 * w],
                     Ag[p] + (size_t)(64 * i) * ldaP[p] + koff);
            cp16(&Bs[buf][lr][4 * w], Wg[p] + koff);
            cp_commit();
        }

        const int buf = t % NST;
        #pragma unroll
        for (int ks = 0; ks < 2; ks++) {
            const int kw0 = ks * 8;
            uint32_t ua[2][4];
            #pragma unroll
            for (int mi = 0; mi < 2; mi++)
                ldsm4(ua[mi][0], ua[mi][1], ua[mi][2], ua[mi][3],
                      &As[buf][a_row + 16 * mi][kw0 + a_wof]);
            uint32_t ub[4][2];
            #pragma unroll
            for (int gp = 0; gp < 2; gp++)
                ldsm4(ub[2 * gp][0], ub[2 * gp][1],
                      ub[2 * gp + 1][0], ub[2 * gp + 1][1],
                      &Bs[buf][b_row + 32 * gp][kw0 + b_wof]);
            #pragma unroll
            for (int mi = 0; mi < 2; mi++)
                #pragma unroll
                for (int g = 0; g < 4; g++)
                    mma16(acc[mi][g], ua[mi], ub[g]);
        }
    }

    // ---- epilogue ----
    #pragma unroll
    for (int mi = 0; mi < 2; mi++) {
        #pragma unroll
        for (int half = 0; half < 2; half++) {
            const int row = 32 * wm + 16 * mi + gid + 8 * half;
            const int b = m0 + row;
            #pragma unroll
            for (int cc = 0; cc < 2; cc++) {
                const int reg = 2 * half + cc;
                const int rl = 8 * wn + 2 * tig + cc;
                if constexpr (EPI == 0) {
                    #pragma unroll
                    for (int g = 0; g < 4; g++) {
                        const int col = nbase + g * gstride + rl;
                        houtf[(size_t)b * ldh + col] = acc[mi][g][reg] + e0[col] + e1[col];
                    }
                } else {
                    const int r = nbase + rl;
                    float pre[4];
                    #pragma unroll
                    for (int g = 0; g < 4; g++) {
                        float base;
                        if constexpr (EPI == 1)
                            base = e0[(size_t)b * PRELD + g * RR + r];
                        else
                            base = e0[g * RR + r] + e1[g * RR + r];
                        pre[g] = acc[mi][g][reg] + base;
                    }
                    const float cprev = cst[b * RR + r];
                    const float iv = sigm(pre[0]);
                    const float fv = sigm(pre[1]);
                    const float ov = sigm(pre[2]);
                    const float gv = tanhf(pre[3]);
                    const float cnew = fv * cprev + iv * gv;
                    const float hnew = ov * tanhf(cnew);
                    cst[b * RR + r] = cnew;
                    houtb[b * RR + r] = __float2bfloat16_rn(hnew);
                    if constexpr (EPI == 2)
                        houtf[(size_t)b * ldh + r] = hnew;
                }
            }
        }
    }
}

// ---- kernels ----

#define SMEM_DECL \
    __shared__ uint32_t As[NST][BM][AW]; \
    __shared__ uint32_t Bs[NST][64][AW];

__global__ __launch_bounds__(256, 2)
void k_pre(const float* __restrict__ bi0, const float* __restrict__ bh0,
           float* __restrict__ preX)
{
    SMEM_DECL
    const int rg = blockIdx.y * 16;
    const int u = rg >> 10, rb = rg & 1023;
    const int nbase = u * 4096 + rb;
    gemm_body<0, 1>(As, Bs, blockIdx.x * BM, nbase,
                    g_xb, II, g_Wi0b, nullptr, 0, nullptr,
                    II, RR, bi0, bh0, nullptr, preX, PRELD, nullptr);
}

__global__ __launch_bounds__(256, 2)
void k_l0(const __nv_bfloat16* __restrict__ h0cur, const __nv_bfloat16* __restrict__ Wh0u,
          const float* __restrict__ preXu, float* __restrict__ c0,
          __nv_bfloat16* __restrict__ h0nxt)
{
    SMEM_DECL
    gemm_body<1, 1>(As, Bs, blockIdx.x * BM, blockIdx.y * 16,
                    h0cur, RR, Wh0u, nullptr, 0, nullptr,
                    RR, RR, preXu, nullptr, c0, nullptr, 0, h0nxt);
}

__global__ __launch_bounds__(256, 2)
void k_l1(const __nv_bfloat16* __restrict__ h0cur, const __nv_bfloat16* __restrict__ Wi1u,
          const __nv_bfloat16* __restrict__ h1in, const __nv_bfloat16* __restrict__ Wh1u,
          const float* __restrict__ bi1u, const float* __restrict__ bh1u,
          float* __restrict__ c1, float* __restrict__ h1outf,
          __nv_bfloat16* __restrict__ h1outb)
{
    SMEM_DECL
    gemm_body<2, 2>(As, Bs, blockIdx.x * BM, blockIdx.y * 16,
                    h0cur, RR, Wi1u, h1in, RR, Wh1u,
                    RR, RR, bi1u, bh1u, c1, h1outf, OUTLD, h1outb);
}

// Combined step + shadow convert:
//   y < 64   : L1(u)  (K=2048)
//   y 64..127: L0(u+1) (K=1024)
//   y >= 128 : convert NEXT step's Wi1/Wh1 fp32->bf16 (batched MLP=CVU)
// Grid (2, 128 + NCVT_CTAS/2) = 296 CTAs = one full wave at 2 CTAs/SM.
__global__ __launch_bounds__(256, 2)
void k_step(const __nv_bfloat16* __restrict__ h0cur, __nv_bfloat16* __restrict__ h0nxt,
            const __nv_bfloat16* __restrict__ Wi1u, const __nv_bfloat16* __restrict__ Wh1u,
            const float* __restrict__ bi1u, const float* __restrict__ bh1u,
            const __nv_bfloat16* __restrict__ h1in, float* __restrict__ h1outf,
            __nv_bfloat16* __restrict__ h1outb,
            const __nv_bfloat16* __restrict__ Wh0n, const float* __restrict__ preXn,
            float* __restrict__ c0, float* __restrict__ c1,
            const float4* __restrict__ cs0, uint2* __restrict__ cd0,
            const float4* __restrict__ cs1, uint2* __restrict__ cd1)
{
    const int y = blockIdx.y;
    if (y >= 128) {
        const int cid  = blockIdx.x * (NCVT_CTAS / 2) + (y - 128);
        const int nthr = NCVT_CTAS * 256;
        const int t0   = cid * 256 + threadIdx.x;
        const int n4   = WBLK / 4;
        #pragma unroll 1
        for (int b = 0; b < 2; b++) {
            const float4* s = (b == 0) ? cs0 : cs1;
            uint2*        d = (b == 0) ? cd0 : cd1;
            #pragma unroll 1
            for (int i = t0; i < n4; i += nthr * CVU) {
                float4 v[CVU];
                #pragma unroll
                for (int j = 0; j < CVU; j++) {
                    const int idx = i + j * nthr;
                    if (idx < n4) v[j] = s[idx];
                }
                #pragma unroll
                for (int j = 0; j < CVU; j++) {
                    const int idx = i + j * nthr;
                    if (idx < n4) d[idx] = pack_bf16x4(v[j]);
                }
            }
        }
        return;
    }
    SMEM_DECL
    const int m0 = blockIdx.x * BM;
    if (y < 64) {
        gemm_body<2, 2>(As, Bs, m0, y * 16,
                        h0cur, RR, Wi1u, h1in, RR, Wh1u,
                        RR, RR, bi1u, bh1u, c1, h1outf, OUTLD, h1outb);
    } else {
        gemm_body<1, 1>(As, Bs, m0, (y - 64) * 16,
                        h0cur, RR, Wh0n, nullptr, 0, nullptr,
                        RR, RR, preXn, nullptr, c0, nullptr, 0, h0nxt);
    }
}

// One merged fp32->bf16 convert over all upfront regions (compile-time bounds):
//   [0, C0): x   [C0, C1): Wi0   [C1, C2): Wh0(all)   [C2, C3): Wi1[0]   [C3, C4): Wh1[0]
__global__ void k_cvt_all(const float4* __restrict__ sx,   uint2* __restrict__ dx,
                          const float4* __restrict__ si0,  uint2* __restrict__ di0,
                          const float4* __restrict__ sh0,  uint2* __restrict__ dh0,
                          const float4* __restrict__ si1,  uint2* __restrict__ di1,
                          const float4* __restrict__ sh1,  uint2* __restrict__ dh1)
{
    int i = blockIdx.x * blockDim.x + threadIdx.x;
    if (i >= CV_C4) return;
    const float4* s; uint2* d; int o;
    if      (i < CV_C0) { s = sx;  d = dx;  o = i; }
    else if (i < CV_C1) { s = si0; d = di0; o = i - CV_C0; }
    else if (i < CV_C2) { s = sh0; d = dh0; o = i - CV_C1; }
    else if (i < CV_C3) { s = si1; d = di1; o = i - CV_C2; }
    else                { s = sh1; d = dh1; o = i - CV_C3; }
    d[o] = pack_bf16x4(s[o]);
}

__global__ void init_states(const float* __restrict__ st, float* __restrict__ out) {
    int idx = blockIdx.x * blockDim.x + threadIdx.x;
    if (idx >= BB * RR) return;
    int b = idx >> 10, r = idx & (RR - 1);
    const float* s = st + (size_t)b * (4 * RR);
    g_h0b[0][idx] = __float2bfloat16_rn(s[r]);
    g_c0[idx]     = s[RR + r];
    float h1 = s[2 * RR + r];
    g_h1b[0][idx] = __float2bfloat16_rn(h1);
    out[(size_t)b * OUTLD + r] = h1;
    g_c1[idx]     = s[3 * RR + r];
}

extern "C" void kernel_launch(void* const* d_in, const int* in_sizes, int n_in,
                              void* d_out, int out_size)
{
    const float* x   = (const float*)d_in[0];
    const float* ini = (const float*)d_in[1];
    const float* Wi0 = (const float*)d_in[2];
    const float* bi0 = (const float*)d_in[3];
    const float* Wh0 = (const float*)d_in[4];
    const float* bh0 = (const float*)d_in[5];
    const float* Wi1 = (const float*)d_in[6];
    const float* bi1 = (const float*)d_in[7];
    const float* Wh1 = (const float*)d_in[8];
    const float* bh1 = (const float*)d_in[9];
    float* out = (float*)d_out;

    float *preX, *c0, *c1;
    __nv_bfloat16 *wi0b, *wh0b, *wi1b, *wh1b, *xb, *h0b, *h1b;
    cudaGetSymbolAddress((void**)&preX, g_preX);
    cudaGetSymbolAddress((void**)&c0,   g_c0);
    cudaGetSymbolAddress((void**)&c1,   g_c1);
    cudaGetSymbolAddress((void**)&wi0b, g_Wi0b);
    cudaGetSymbolAddress((void**)&wh0b, g_Wh0b);
    cudaGetSymbolAddress((void**)&wi1b, g_Wi1b);
    cudaGetSymbolAddress((void**)&wh1b, g_Wh1b);
    cudaGetSymbolAddress((void**)&xb,   g_xb);
    cudaGetSymbolAddress((void**)&h0b,  g_h0b);
    cudaGetSymbolAddress((void**)&h1b,  g_h1b);

    auto h0p = [&](int i) { return h0b + (size_t)i * BB * RR; };
    auto h1p = [&](int i) { return h1b + (size_t)i * BB * RR; };

    // ---- single merged upfront convert ----
    k_cvt_all<<<(CV_C4 + 255) / 256, 256>>>(
        (const float4*)x,   (uint2*)xb,
        (const float4*)Wi0, (uint2*)wi0b,
        (const float4*)Wh0, (uint2*)wh0b,
        (const float4*)Wi1, (uint2*)wi1b,
        (const float4*)Wh1, (uint2*)wh1b);

    init_states<<<(BB * RR) / 256, 256>>>(ini, out);

    // PreX = x @ Wi0[0:10].T + bi0 + bh0
    k_pre<<<dim3(BB / BM, PRELD / 64), 256>>>(bi0, bh0, preX);

    // L0(0)
    k_l0<<<dim3(BB / BM, RR / 16), 256>>>(h0p(0), wh0b, preX, c0, h0p(1));

    // C(u) = L1(u) + L0(u+1) + shadow-convert(Wi1[u+1], Wh1[u+1]), u = 0..8
    for (int u = 0; u < NSTEP - 1; u++) {
        const size_t wo  = (size_t)u * WBLK;
        const size_t wn_ = (size_t)(u + 1) * WBLK;
        const size_t bo  = (size_t)u * 4 * RR;
        k_step<<<dim3(BB / BM, 128 + NCVT_CTAS / 2), 256>>>(
            h0p((u + 1) & 1), h0p(u & 1),
            wi1b + wo, wh1b + wo, bi1 + bo, bh1 + bo,
            h1p(u & 1), out + (size_t)(u + 1) * RR, h1p((u + 1) & 1),
            wh0b + wn_, preX + (size_t)(u + 1) * 4 * RR,
            c0, c1,
            (const float4*)(Wi1 + wn_), (uint2*)(wi1b + wn_),
            (const float4*)(Wh1 + wn_), (uint2*)(wh1b + wn_));
    }

    // final L1(9)  (Wi1[9]/Wh1[9] converted inside k_step(8))
    {
        const int u = NSTEP - 1;
        const size_t wo = (size_t)u * WBLK;
        const size_t bo = (size_t)u * 4 * RR;
        k_l1<<<dim3(BB / BM, RR / 16), 256>>>(
            h0p((u + 1) & 1), wi1b + wo,
            h1p(u & 1), wh1b + wo,
            bi1 + bo, bh1 + bo,
            c1, out + (size_t)(u + 1) * RR, h1p((u + 1) & 1));
    }
}